// round 4
// baseline (speedup 1.0000x reference)
#include <cuda_runtime.h>
#include <cuda_fp16.h>
#include <cstdint>

// Y = X @ (W_nf4 * c1 * c_kbit_2) + (X@L1)@L2
// Folded-K formulation (4096 + 16 lora + 48 zero pad = 4160):
//   Xe fp16 [8192,4160] = [fp16(X) | fp16(X@L1) | 0]
//   We fp16 [4096,4160] = [fp16(W^T) | fp16(L2^T) | 0]   (K contiguous per N row)
// GEMM via mma.sync.m16n8k16 (tcgen05 unavailable: harness PTX target is plain
// sm_103 which rejects 'a'-suffix instructions).
// R3->R4: BN 256->128, S 4->3, warp tile 64x64->64x32 => 2 CTAs/SM so the
// per-iteration CP_WAIT+barrier bubbles of one CTA overlap the other's MMAs.

static constexpr int D_IN  = 4096;
static constexpr int D_OUT = 4096;
static constexpr int NROWS = 8192;
static constexpr int KPAD  = 4160;

static constexpr int BM = 128, BN = 128, BK = 64, S = 3;
static constexpr int KT = KPAD / BK;              // 65
static constexpr int ABYTES = BM * BK * 2;        // 16384
static constexpr int BBYTES = BN * BK * 2;        // 16384
static constexpr int STAGE  = ABYTES + BBYTES;    // 32768
static constexpr int SMEM_SZ = S * STAGE;         // 98304 per CTA (2 CTAs/SM)

__device__ __align__(16) __half g_Xe[(size_t)NROWS * KPAD];   // 68 MB
__device__ __align__(16) __half g_We[(size_t)D_OUT * KPAD];   // 34 MB

// ------------------------------ PTX helpers -------------------------------
__device__ __forceinline__ void cp16(uint32_t dst, const void* src) {
    asm volatile("cp.async.cg.shared.global [%0], [%1], 16;"
                 :: "r"(dst), "l"(__cvta_generic_to_global(src)) : "memory");
}
#define CP_COMMIT() asm volatile("cp.async.commit_group;" ::: "memory")
#define CP_WAIT(n)  asm volatile("cp.async.wait_group %0;" :: "n"(n) : "memory")

#define LDSM4(r, a) \
    asm volatile("ldmatrix.sync.aligned.m8n8.x4.shared.b16 {%0,%1,%2,%3}, [%4];" \
        : "=r"((r)[0]), "=r"((r)[1]), "=r"((r)[2]), "=r"((r)[3]) : "r"(a))

#define MMA16816(d, a, b) \
    asm volatile("mma.sync.aligned.m16n8k16.row.col.f32.f16.f16.f32 " \
        "{%0,%1,%2,%3}, {%4,%5,%6,%7}, {%8,%9}, {%0,%1,%2,%3};" \
        : "+f"((d)[0]), "+f"((d)[1]), "+f"((d)[2]), "+f"((d)[3]) \
        : "r"((a)[0]), "r"((a)[1]), "r"((a)[2]), "r"((a)[3]), \
          "r"((b)[0]), "r"((b)[1]))

__device__ __forceinline__ uint32_t swz(uint32_t o) { return o ^ ((o >> 3) & 0x70); }

// ----------------------- pack_X: fp16(X) and X@L1 -------------------------
__global__ void __launch_bounds__(256, 2)
pack_x_kernel(const float* __restrict__ X, const float* __restrict__ L1) {
    __shared__ float sL1[512 * 17];
    const int tid = threadIdx.x, lane = tid & 31, warp = tid >> 5;
    const int rowbase = blockIdx.x * 32 + warp * 4;

    float acc[4][16];
#pragma unroll
    for (int r = 0; r < 4; r++)
#pragma unroll
        for (int j = 0; j < 16; j++) acc[r][j] = 0.f;

    for (int ch = 0; ch < 8; ch++) {
        const int k0 = ch * 512;
#pragma unroll
        for (int i = 0; i < 32; i++) {
            int idx = tid + i * 256;
            int kk = idx >> 4, j = idx & 15;
            sL1[kk * 17 + j] = L1[(size_t)(k0 + kk) * 16 + j];
        }
        __syncthreads();

#pragma unroll 4
        for (int ii = 0; ii < 16; ii++) {
            const int kk = ii * 32 + lane;
            const int k  = k0 + kk;
            float xs[4];
#pragma unroll
            for (int r = 0; r < 4; r++) {
                float v = X[(size_t)(rowbase + r) * D_IN + k];
                xs[r] = v;
                g_Xe[(size_t)(rowbase + r) * KPAD + k] = __float2half_rn(v);
            }
            const float* lp = sL1 + kk * 17;
#pragma unroll
            for (int j = 0; j < 16; j++) {
                float lv = lp[j];
#pragma unroll
                for (int r = 0; r < 4; r++) acc[r][j] += xs[r] * lv;
            }
        }
        __syncthreads();
    }

#pragma unroll
    for (int r = 0; r < 4; r++) {
#pragma unroll
        for (int j = 0; j < 16; j++) {
            float v = acc[r][j];
            v += __shfl_xor_sync(0xffffffffu, v, 16);
            v += __shfl_xor_sync(0xffffffffu, v, 8);
            v += __shfl_xor_sync(0xffffffffu, v, 4);
            v += __shfl_xor_sync(0xffffffffu, v, 2);
            v += __shfl_xor_sync(0xffffffffu, v, 1);
            acc[r][j] = v;
        }
        const int row = rowbase + r;
        if (lane == 0) {
#pragma unroll
            for (int j = 0; j < 16; j++)
                g_Xe[(size_t)row * KPAD + 4096 + j] = __float2half_rn(acc[r][j]);
        }
        if (lane < 6)
            *(uint4*)(g_Xe + (size_t)row * KPAD + 4112 + (size_t)lane * 8) =
                make_uint4(0, 0, 0, 0);
    }
}

// ------------------ pack_W: dequant + transpose to We ----------------------
__global__ void __launch_bounds__(256)
pack_w_kernel(const float* __restrict__ Wq, const float* __restrict__ c1p,
              const float* __restrict__ ck) {
    __shared__ float tile[64 * 65];
    const float c1 = *c1p;
    const int tid = threadIdx.x;
    const int n0 = blockIdx.x * 64, k0 = blockIdx.y * 64;
    const int cidx = tid & 63, ridx = tid >> 6;

#pragma unroll
    for (int ro = 0; ro < 16; ro++) {
        int kk = ro * 4 + ridx;
        size_t g = (size_t)(k0 + kk) * D_OUT + n0 + cidx;
        tile[kk * 65 + cidx] = Wq[g] * c1 * ck[g];
    }
    __syncthreads();
#pragma unroll
    for (int ro = 0; ro < 16; ro++) {
        int nn = ro * 4 + ridx;
        g_We[(size_t)(n0 + nn) * KPAD + k0 + cidx] =
            __float2half_rn(tile[cidx * 65 + nn]);
    }
}

// ------------------ pack_tail: L2 rows + zero-pad cols ---------------------
__global__ void __launch_bounds__(256)
pack_tail_kernel(const float* __restrict__ L2) {
    int idx = blockIdx.x * 256 + threadIdx.x;   // 4096 * 64
    int n = idx >> 6, kk = idx & 63;
    __half v = (kk < 16) ? __float2half_rn(L2[(size_t)kk * D_OUT + n]) : __half(0.f);
    g_We[(size_t)n * KPAD + 4096 + kk] = v;
}

// ------------------------------ GEMM kernel --------------------------------
// 256 threads = 8 warps: wm = wid&1 (2 x 64 rows), wn = wid>>1 (4 x 32 cols).
// Warp tile 64x32, mma.m16n8k16, 3-stage cp.async pipeline, 2 CTAs/SM.
__global__ void __launch_bounds__(256, 2)
gemm_kernel(float* __restrict__ Y) {
    extern __shared__ char smem[];
    const uint32_t sb = (uint32_t)__cvta_generic_to_shared(smem);
    const int tid = threadIdx.x, wid = tid >> 5, lane = tid & 31;
    const int m0 = blockIdx.y * BM, n0 = blockIdx.x * BN;
    const int wm = wid & 1, wn = wid >> 1;
    const int gid = lane >> 2, tig = lane & 3;

    auto loadA = [&](int kt, int slot) {
        const __half* src = g_Xe + (size_t)m0 * KPAD + (size_t)kt * BK;
        uint32_t base = sb + slot * STAGE;
#pragma unroll
        for (int i = 0; i < 4; i++) {
            int idx = tid + i * 256;                 // 1024 16B chunks
            int r = idx >> 3, c = idx & 7;
            cp16(base + swz((uint32_t)(r * 128 + c * 16)),
                 src + (size_t)r * KPAD + c * 8);
        }
    };
    auto loadB = [&](int kt, int slot) {
        const __half* src = g_We + (size_t)n0 * KPAD + (size_t)kt * BK;
        uint32_t base = sb + slot * STAGE + ABYTES;
#pragma unroll
        for (int i = 0; i < 4; i++) {
            int idx = tid + i * 256;                 // 1024 16B chunks
            int r = idx >> 3, c = idx & 7;
            cp16(base + swz((uint32_t)(r * 128 + c * 16)),
                 src + (size_t)r * KPAD + c * 8);
        }
    };

    float acc[4][4][4];
#pragma unroll
    for (int t = 0; t < 4; t++)
#pragma unroll
        for (int n = 0; n < 4; n++)
#pragma unroll
            for (int j = 0; j < 4; j++) acc[t][n][j] = 0.f;

    // Prologue: stages 0..S-2
#pragma unroll
    for (int s = 0; s < S - 1; s++) { loadA(s, s); loadB(s, s); CP_COMMIT(); }

    // ldmatrix lane addressing (constant per thread, relative to stage base)
    const uint32_t a_row = (uint32_t)(wm * 64 + (lane & 15));
    const uint32_t a_chk = (uint32_t)(lane >> 4);
    const uint32_t b_row = (uint32_t)(wn * 32 + ((lane >> 4) & 1) * 8 + (lane & 7));
    const uint32_t b_chk = (uint32_t)((lane >> 3) & 1);

    for (int kt = 0; kt < KT; kt++) {
        CP_WAIT(S - 2);            // stage kt complete
        __syncthreads();           // all warps done reading the slot we refill

        if (kt + S - 1 < KT) { loadA(kt + S - 1, (kt + S - 1) % S);
                               loadB(kt + S - 1, (kt + S - 1) % S); }
        CP_COMMIT();               // keep group arithmetic uniform

        const uint32_t abase = sb + (kt % S) * STAGE;
        const uint32_t bbase = abase + ABYTES;

#pragma unroll
        for (int ks = 0; ks < 4; ks++) {
            uint32_t af[4][4];
#pragma unroll
            for (int t = 0; t < 4; t++) {
                uint32_t off = (a_row + t * 16) * 128 + (a_chk + ks * 2) * 16;
                LDSM4(af[t], abase + swz(off));
            }
            uint32_t bf[4][2];
#pragma unroll
            for (int g = 0; g < 2; g++) {
                uint32_t off = (b_row + g * 16) * 128 + (b_chk + ks * 2) * 16;
                uint32_t r[4];
                LDSM4(r, bbase + swz(off));
                bf[2 * g][0] = r[0]; bf[2 * g][1] = r[1];
                bf[2 * g + 1][0] = r[2]; bf[2 * g + 1][1] = r[3];
            }
#pragma unroll
            for (int t = 0; t < 4; t++)
#pragma unroll
                for (int n = 0; n < 4; n++)
                    MMA16816(acc[t][n], af[t], bf[n]);
        }
    }

    // Epilogue: direct float2 stores
#pragma unroll
    for (int t = 0; t < 4; t++) {
        const int r0 = m0 + wm * 64 + t * 16 + gid;
        float* y0 = Y + (size_t)r0 * D_OUT + n0 + wn * 32 + tig * 2;
        float* y1 = y0 + (size_t)8 * D_OUT;
#pragma unroll
        for (int n = 0; n < 4; n++) {
            *(float2*)(y0 + n * 8) = make_float2(acc[t][n][0], acc[t][n][1]);
            *(float2*)(y1 + n * 8) = make_float2(acc[t][n][2], acc[t][n][3]);
        }
    }
}

// ------------------------------- launcher ----------------------------------
extern "C" void kernel_launch(void* const* d_in, const int* in_sizes, int n_in,
                              void* d_out, int out_size) {
    const float* X  = (const float*)d_in[0];
    const float* Wq = (const float*)d_in[1];
    const float* c1 = (const float*)d_in[2];
    const float* ck = (const float*)d_in[3];
    const float* L1 = (const float*)d_in[4];
    const float* L2 = (const float*)d_in[5];
    float* Y = (float*)d_out;

    cudaFuncSetAttribute(gemm_kernel, cudaFuncAttributeMaxDynamicSharedMemorySize, SMEM_SZ);

    pack_x_kernel<<<NROWS / 32, 256>>>(X, L1);
    pack_w_kernel<<<dim3(D_OUT / 64, D_IN / 64), 256>>>(Wq, c1, ck);
    pack_tail_kernel<<<(D_OUT * 64) / 256, 256>>>(L2);
    gemm_kernel<<<dim3(D_OUT / BN, NROWS / BM), 256, SMEM_SZ>>>(Y);
}

// round 5
// speedup vs baseline: 1.0227x; 1.0227x over previous
#include <cuda_runtime.h>
#include <cuda_fp16.h>
#include <cstdint>

// Y = X @ (W_nf4 * c1 * c_kbit_2) + (X@L1)@L2
// Folded-K formulation (4096 + 16 lora + 48 zero pad = 4160):
//   Xe fp16 [8192,4160] = [fp16(X) | fp16(X@L1) | 0]
//   We fp16 [4096,4160] = [fp16(W^T) | fp16(L2^T) | 0]   (K contiguous per N row)
// GEMM via mma.sync.m16n8k16 (tcgen05 unavailable at plain sm_103 PTX target).
// R4->R5: the ~72% tensor cap is lockstep LDSM bursts serializing on the smem
// crossbar while the tensor pipe idles. Fix: 4-warp CTA (64x64 warp tile,
// BM=BN=128) with DOUBLE-BUFFERED ldmatrix fragments so ks+1 LDSMs interleave
// with ks MMAs. S=3 (96KB smem) => 2 CTAs/SM.

static constexpr int D_IN  = 4096;
static constexpr int D_OUT = 4096;
static constexpr int NROWS = 8192;
static constexpr int KPAD  = 4160;

static constexpr int BM = 128, BN = 128, BK = 64, S = 3;
static constexpr int KT = KPAD / BK;              // 65
static constexpr int ABYTES = BM * BK * 2;        // 16384
static constexpr int BBYTES = BN * BK * 2;        // 16384
static constexpr int STAGE  = ABYTES + BBYTES;    // 32768
static constexpr int SMEM_SZ = S * STAGE;         // 98304 (2 CTAs/SM)

__device__ __align__(16) __half g_Xe[(size_t)NROWS * KPAD];   // 68 MB
__device__ __align__(16) __half g_We[(size_t)D_OUT * KPAD];   // 34 MB

// ------------------------------ PTX helpers -------------------------------
__device__ __forceinline__ void cp16(uint32_t dst, const void* src) {
    asm volatile("cp.async.cg.shared.global [%0], [%1], 16;"
                 :: "r"(dst), "l"(__cvta_generic_to_global(src)) : "memory");
}
#define CP_COMMIT() asm volatile("cp.async.commit_group;" ::: "memory")
#define CP_WAIT(n)  asm volatile("cp.async.wait_group %0;" :: "n"(n) : "memory")

#define LDSM4(r, a) \
    asm volatile("ldmatrix.sync.aligned.m8n8.x4.shared.b16 {%0,%1,%2,%3}, [%4];" \
        : "=r"((r)[0]), "=r"((r)[1]), "=r"((r)[2]), "=r"((r)[3]) : "r"(a))

#define MMA16816(d, a, b) \
    asm volatile("mma.sync.aligned.m16n8k16.row.col.f32.f16.f16.f32 " \
        "{%0,%1,%2,%3}, {%4,%5,%6,%7}, {%8,%9}, {%0,%1,%2,%3};" \
        : "+f"((d)[0]), "+f"((d)[1]), "+f"((d)[2]), "+f"((d)[3]) \
        : "r"((a)[0]), "r"((a)[1]), "r"((a)[2]), "r"((a)[3]), \
          "r"((b)[0]), "r"((b)[1]))

__device__ __forceinline__ uint32_t swz(uint32_t o) { return o ^ ((o >> 3) & 0x70); }

// ----------------------- pack_X: fp16(X) and X@L1 -------------------------
__global__ void __launch_bounds__(256, 2)
pack_x_kernel(const float* __restrict__ X, const float* __restrict__ L1) {
    __shared__ float sL1[512 * 17];
    const int tid = threadIdx.x, lane = tid & 31, warp = tid >> 5;
    const int rowbase = blockIdx.x * 32 + warp * 4;

    float acc[4][16];
#pragma unroll
    for (int r = 0; r < 4; r++)
#pragma unroll
        for (int j = 0; j < 16; j++) acc[r][j] = 0.f;

    for (int ch = 0; ch < 8; ch++) {
        const int k0 = ch * 512;
#pragma unroll
        for (int i = 0; i < 32; i++) {
            int idx = tid + i * 256;
            int kk = idx >> 4, j = idx & 15;
            sL1[kk * 17 + j] = L1[(size_t)(k0 + kk) * 16 + j];
        }
        __syncthreads();

#pragma unroll 4
        for (int ii = 0; ii < 16; ii++) {
            const int kk = ii * 32 + lane;
            const int k  = k0 + kk;
            float xs[4];
#pragma unroll
            for (int r = 0; r < 4; r++) {
                float v = X[(size_t)(rowbase + r) * D_IN + k];
                xs[r] = v;
                g_Xe[(size_t)(rowbase + r) * KPAD + k] = __float2half_rn(v);
            }
            const float* lp = sL1 + kk * 17;
#pragma unroll
            for (int j = 0; j < 16; j++) {
                float lv = lp[j];
#pragma unroll
                for (int r = 0; r < 4; r++) acc[r][j] += xs[r] * lv;
            }
        }
        __syncthreads();
    }

#pragma unroll
    for (int r = 0; r < 4; r++) {
#pragma unroll
        for (int j = 0; j < 16; j++) {
            float v = acc[r][j];
            v += __shfl_xor_sync(0xffffffffu, v, 16);
            v += __shfl_xor_sync(0xffffffffu, v, 8);
            v += __shfl_xor_sync(0xffffffffu, v, 4);
            v += __shfl_xor_sync(0xffffffffu, v, 2);
            v += __shfl_xor_sync(0xffffffffu, v, 1);
            acc[r][j] = v;
        }
        const int row = rowbase + r;
        if (lane == 0) {
#pragma unroll
            for (int j = 0; j < 16; j++)
                g_Xe[(size_t)row * KPAD + 4096 + j] = __float2half_rn(acc[r][j]);
        }
        if (lane < 6)
            *(uint4*)(g_Xe + (size_t)row * KPAD + 4112 + (size_t)lane * 8) =
                make_uint4(0, 0, 0, 0);
    }
}

// ------------------ pack_W: dequant + transpose to We ----------------------
__global__ void __launch_bounds__(256)
pack_w_kernel(const float* __restrict__ Wq, const float* __restrict__ c1p,
              const float* __restrict__ ck) {
    __shared__ float tile[64 * 65];
    const float c1 = *c1p;
    const int tid = threadIdx.x;
    const int n0 = blockIdx.x * 64, k0 = blockIdx.y * 64;
    const int cidx = tid & 63, ridx = tid >> 6;

#pragma unroll
    for (int ro = 0; ro < 16; ro++) {
        int kk = ro * 4 + ridx;
        size_t g = (size_t)(k0 + kk) * D_OUT + n0 + cidx;
        tile[kk * 65 + cidx] = Wq[g] * c1 * ck[g];
    }
    __syncthreads();
#pragma unroll
    for (int ro = 0; ro < 16; ro++) {
        int nn = ro * 4 + ridx;
        g_We[(size_t)(n0 + nn) * KPAD + k0 + cidx] =
            __float2half_rn(tile[cidx * 65 + nn]);
    }
}

// ------------------ pack_tail: L2 rows + zero-pad cols ---------------------
__global__ void __launch_bounds__(256)
pack_tail_kernel(const float* __restrict__ L2) {
    int idx = blockIdx.x * 256 + threadIdx.x;   // 4096 * 64
    int n = idx >> 6, kk = idx & 63;
    __half v = (kk < 16) ? __float2half_rn(L2[(size_t)kk * D_OUT + n]) : __half(0.f);
    g_We[(size_t)n * KPAD + 4096 + kk] = v;
}

// ------------------------------ GEMM kernel --------------------------------
// 128 threads = 4 warps (2x2): wm = wid&1 (64 rows), wn = wid>>1 (64 cols).
// Warp tile 64x64. Fragment double-buffering: LDSM(ks+1) interleaves MMA(ks).
__global__ void __launch_bounds__(128, 2)
gemm_kernel(float* __restrict__ Y) {
    extern __shared__ char smem[];
    const uint32_t sb = (uint32_t)__cvta_generic_to_shared(smem);
    const int tid = threadIdx.x, wid = tid >> 5, lane = tid & 31;
    const int m0 = blockIdx.y * BM, n0 = blockIdx.x * BN;
    const int wm = wid & 1, wn = wid >> 1;
    const int gid = lane >> 2, tig = lane & 3;

    auto loadA = [&](int kt, int slot) {
        const __half* src = g_Xe + (size_t)m0 * KPAD + (size_t)kt * BK;
        uint32_t base = sb + slot * STAGE;
#pragma unroll
        for (int i = 0; i < 8; i++) {
            int idx = tid + i * 128;                 // 1024 16B chunks
            int r = idx >> 3, c = idx & 7;
            cp16(base + swz((uint32_t)(r * 128 + c * 16)),
                 src + (size_t)r * KPAD + c * 8);
        }
    };
    auto loadB = [&](int kt, int slot) {
        const __half* src = g_We + (size_t)n0 * KPAD + (size_t)kt * BK;
        uint32_t base = sb + slot * STAGE + ABYTES;
#pragma unroll
        for (int i = 0; i < 8; i++) {
            int idx = tid + i * 128;                 // 1024 16B chunks
            int r = idx >> 3, c = idx & 7;
            cp16(base + swz((uint32_t)(r * 128 + c * 16)),
                 src + (size_t)r * KPAD + c * 8);
        }
    };

    float acc[4][8][4];
#pragma unroll
    for (int t = 0; t < 4; t++)
#pragma unroll
        for (int n = 0; n < 8; n++)
#pragma unroll
            for (int j = 0; j < 4; j++) acc[t][n][j] = 0.f;

#pragma unroll
    for (int s = 0; s < S - 1; s++) { loadA(s, s); loadB(s, s); CP_COMMIT(); }

    // ldmatrix lane addressing (relative to stage base)
    const uint32_t a_row = (uint32_t)(wm * 64 + (lane & 15));
    const uint32_t a_chk = (uint32_t)(lane >> 4);
    const uint32_t b_row = (uint32_t)(wn * 64 + ((lane >> 4) & 1) * 8 + (lane & 7));
    const uint32_t b_chk = (uint32_t)((lane >> 3) & 1);

    uint32_t af[2][4][4];   // double-buffered A fragments
    uint32_t bf[2][8][2];   // double-buffered B fragments

    auto load_frag = [&](int buf, uint32_t abase, uint32_t bbase, int ks) {
#pragma unroll
        for (int t = 0; t < 4; t++) {
            uint32_t off = (a_row + t * 16) * 128 + (a_chk + ks * 2) * 16;
            LDSM4(af[buf][t], abase + swz(off));
        }
#pragma unroll
        for (int g = 0; g < 4; g++) {
            uint32_t off = (b_row + g * 16) * 128 + (b_chk + ks * 2) * 16;
            uint32_t r[4];
            LDSM4(r, bbase + swz(off));
            bf[buf][2 * g][0] = r[0];     bf[buf][2 * g][1] = r[1];
            bf[buf][2 * g + 1][0] = r[2]; bf[buf][2 * g + 1][1] = r[3];
        }
    };

    for (int kt = 0; kt < KT; kt++) {
        CP_WAIT(S - 2);            // stage kt complete
        __syncthreads();           // all warps done reading the slot we refill

        if (kt + S - 1 < KT) { loadA(kt + S - 1, (kt + S - 1) % S);
                               loadB(kt + S - 1, (kt + S - 1) % S); }
        CP_COMMIT();

        const uint32_t abase = sb + (kt % S) * STAGE;
        const uint32_t bbase = abase + ABYTES;

        load_frag(0, abase, bbase, 0);
#pragma unroll
        for (int ks = 0; ks < 4; ks++) {
            const int cur = ks & 1;
            if (ks < 3) load_frag(cur ^ 1, abase, bbase, ks + 1);
#pragma unroll
            for (int t = 0; t < 4; t++)
#pragma unroll
                for (int n = 0; n < 8; n++)
                    MMA16816(acc[t][n], af[cur][t], bf[cur][n]);
        }
    }

    // Epilogue: direct float2 stores
#pragma unroll
    for (int t = 0; t < 4; t++) {
        const int r0 = m0 + wm * 64 + t * 16 + gid;
        float* y0 = Y + (size_t)r0 * D_OUT + n0 + wn * 64 + tig * 2;
        float* y1 = y0 + (size_t)8 * D_OUT;
#pragma unroll
        for (int n = 0; n < 8; n++) {
            *(float2*)(y0 + n * 8) = make_float2(acc[t][n][0], acc[t][n][1]);
            *(float2*)(y1 + n * 8) = make_float2(acc[t][n][2], acc[t][n][3]);
        }
    }
}

// ------------------------------- launcher ----------------------------------
extern "C" void kernel_launch(void* const* d_in, const int* in_sizes, int n_in,
                              void* d_out, int out_size) {
    const float* X  = (const float*)d_in[0];
    const float* Wq = (const float*)d_in[1];
    const float* c1 = (const float*)d_in[2];
    const float* ck = (const float*)d_in[3];
    const float* L1 = (const float*)d_in[4];
    const float* L2 = (const float*)d_in[5];
    float* Y = (float*)d_out;

    cudaFuncSetAttribute(gemm_kernel, cudaFuncAttributeMaxDynamicSharedMemorySize, SMEM_SZ);

    pack_x_kernel<<<NROWS / 32, 256>>>(X, L1);
    pack_w_kernel<<<dim3(D_OUT / 64, D_IN / 64), 256>>>(Wq, c1, ck);
    pack_tail_kernel<<<(D_OUT * 64) / 256, 256>>>(L2);
    gemm_kernel<<<dim3(D_OUT / BN, NROWS / BM), 128, SMEM_SZ>>>(Y);
}

// round 6
// speedup vs baseline: 1.1707x; 1.1447x over previous
#include <cuda_runtime.h>
#include <cuda_fp16.h>
#include <cstdint>

// Y = X @ (W_nf4 * c1 * c_kbit_2) + (X@L1)@L2
// Folded-K: Xe fp16 [8192,4160]=[X | X@L1 | 0], We fp16 [4096,4160]=[W^T | L2^T | 0]
// GEMM via mma.sync.m16n8k16 (tcgen05 rejected at plain sm_103 PTX target).
// R5->R6: all configs pin tensor at ~73% => the idle is the per-iteration
// boundary (first LDSM queued behind the LDGSTS burst + frag fill latency).
// Fix: cross-iteration fragment prefetch (deferred commit_group + wait_group 0
// drains only the previous stage), and issue the cp.async burst AFTER the
// first MMA block instead of before the first ldmatrix.

static constexpr int D_IN  = 4096;
static constexpr int D_OUT = 4096;
static constexpr int NROWS = 8192;
static constexpr int KPAD  = 4160;

static constexpr int BM = 128, BN = 128, BK = 64, S = 3;
static constexpr int KT = KPAD / BK;              // 65
static constexpr int ABYTES = BM * BK * 2;        // 16384
static constexpr int BBYTES = BN * BK * 2;        // 16384
static constexpr int STAGE  = ABYTES + BBYTES;    // 32768
static constexpr int SMEM_SZ = S * STAGE;         // 98304 (2 CTAs/SM)

__device__ __align__(16) __half g_Xe[(size_t)NROWS * KPAD];   // 68 MB
__device__ __align__(16) __half g_We[(size_t)D_OUT * KPAD];   // 34 MB

// ------------------------------ PTX helpers -------------------------------
__device__ __forceinline__ void cp16(uint32_t dst, const void* src) {
    asm volatile("cp.async.cg.shared.global [%0], [%1], 16;"
                 :: "r"(dst), "l"(__cvta_generic_to_global(src)) : "memory");
}
#define CP_COMMIT() asm volatile("cp.async.commit_group;" ::: "memory")
#define CP_WAIT(n)  asm volatile("cp.async.wait_group %0;" :: "n"(n) : "memory")

#define LDSM4(r, a) \
    asm volatile("ldmatrix.sync.aligned.m8n8.x4.shared.b16 {%0,%1,%2,%3}, [%4];" \
        : "=r"((r)[0]), "=r"((r)[1]), "=r"((r)[2]), "=r"((r)[3]) : "r"(a))

#define MMA16816(d, a, b) \
    asm volatile("mma.sync.aligned.m16n8k16.row.col.f32.f16.f16.f32 " \
        "{%0,%1,%2,%3}, {%4,%5,%6,%7}, {%8,%9}, {%0,%1,%2,%3};" \
        : "+f"((d)[0]), "+f"((d)[1]), "+f"((d)[2]), "+f"((d)[3]) \
        : "r"((a)[0]), "r"((a)[1]), "r"((a)[2]), "r"((a)[3]), \
          "r"((b)[0]), "r"((b)[1]))

__device__ __forceinline__ uint32_t swz(uint32_t o) { return o ^ ((o >> 3) & 0x70); }

// ----------------------- pack_X: fp16(X) and X@L1 -------------------------
__global__ void __launch_bounds__(256, 2)
pack_x_kernel(const float* __restrict__ X, const float* __restrict__ L1) {
    __shared__ float sL1[512 * 17];
    const int tid = threadIdx.x, lane = tid & 31, warp = tid >> 5;
    const int rowbase = blockIdx.x * 32 + warp * 4;

    float acc[4][16];
#pragma unroll
    for (int r = 0; r < 4; r++)
#pragma unroll
        for (int j = 0; j < 16; j++) acc[r][j] = 0.f;

    for (int ch = 0; ch < 8; ch++) {
        const int k0 = ch * 512;
#pragma unroll
        for (int i = 0; i < 32; i++) {
            int idx = tid + i * 256;
            int kk = idx >> 4, j = idx & 15;
            sL1[kk * 17 + j] = L1[(size_t)(k0 + kk) * 16 + j];
        }
        __syncthreads();

#pragma unroll 4
        for (int ii = 0; ii < 16; ii++) {
            const int kk = ii * 32 + lane;
            const int k  = k0 + kk;
            float xs[4];
#pragma unroll
            for (int r = 0; r < 4; r++) {
                float v = X[(size_t)(rowbase + r) * D_IN + k];
                xs[r] = v;
                g_Xe[(size_t)(rowbase + r) * KPAD + k] = __float2half_rn(v);
            }
            const float* lp = sL1 + kk * 17;
#pragma unroll
            for (int j = 0; j < 16; j++) {
                float lv = lp[j];
#pragma unroll
                for (int r = 0; r < 4; r++) acc[r][j] += xs[r] * lv;
            }
        }
        __syncthreads();
    }

#pragma unroll
    for (int r = 0; r < 4; r++) {
#pragma unroll
        for (int j = 0; j < 16; j++) {
            float v = acc[r][j];
            v += __shfl_xor_sync(0xffffffffu, v, 16);
            v += __shfl_xor_sync(0xffffffffu, v, 8);
            v += __shfl_xor_sync(0xffffffffu, v, 4);
            v += __shfl_xor_sync(0xffffffffu, v, 2);
            v += __shfl_xor_sync(0xffffffffu, v, 1);
            acc[r][j] = v;
        }
        const int row = rowbase + r;
        if (lane == 0) {
#pragma unroll
            for (int j = 0; j < 16; j++)
                g_Xe[(size_t)row * KPAD + 4096 + j] = __float2half_rn(acc[r][j]);
        }
        if (lane < 6)
            *(uint4*)(g_Xe + (size_t)row * KPAD + 4112 + (size_t)lane * 8) =
                make_uint4(0, 0, 0, 0);
    }
}

// ------------------ pack_W: dequant + transpose to We ----------------------
__global__ void __launch_bounds__(256)
pack_w_kernel(const float* __restrict__ Wq, const float* __restrict__ c1p,
              const float* __restrict__ ck) {
    __shared__ float tile[64 * 65];
    const float c1 = *c1p;
    const int tid = threadIdx.x;
    const int n0 = blockIdx.x * 64, k0 = blockIdx.y * 64;
    const int cidx = tid & 63, ridx = tid >> 6;

#pragma unroll
    for (int ro = 0; ro < 16; ro++) {
        int kk = ro * 4 + ridx;
        size_t g = (size_t)(k0 + kk) * D_OUT + n0 + cidx;
        tile[kk * 65 + cidx] = Wq[g] * c1 * ck[g];
    }
    __syncthreads();
#pragma unroll
    for (int ro = 0; ro < 16; ro++) {
        int nn = ro * 4 + ridx;
        g_We[(size_t)(n0 + nn) * KPAD + k0 + cidx] =
            __float2half_rn(tile[cidx * 65 + nn]);
    }
}

// ------------------ pack_tail: L2 rows + zero-pad cols ---------------------
__global__ void __launch_bounds__(256)
pack_tail_kernel(const float* __restrict__ L2) {
    int idx = blockIdx.x * 256 + threadIdx.x;   // 4096 * 64
    int n = idx >> 6, kk = idx & 63;
    __half v = (kk < 16) ? __float2half_rn(L2[(size_t)kk * D_OUT + n]) : __half(0.f);
    g_We[(size_t)n * KPAD + 4096 + kk] = v;
}

// ------------------------------ GEMM kernel --------------------------------
// 128 threads = 4 warps (2x2), warp tile 64x64, cross-iteration frag prefetch.
__global__ void __launch_bounds__(128, 2)
gemm_kernel(float* __restrict__ Y) {
    extern __shared__ char smem[];
    const uint32_t sb = (uint32_t)__cvta_generic_to_shared(smem);
    const int tid = threadIdx.x, wid = tid >> 5, lane = tid & 31;
    const int m0 = blockIdx.y * BM, n0 = blockIdx.x * BN;
    const int wm = wid & 1, wn = wid >> 1;
    const int gid = lane >> 2, tig = lane & 3;

    auto loadA = [&](int kt, int slot) {
        const __half* src = g_Xe + (size_t)m0 * KPAD + (size_t)kt * BK;
        uint32_t base = sb + slot * STAGE;
#pragma unroll
        for (int i = 0; i < 8; i++) {
            int idx = tid + i * 128;
            int r = idx >> 3, c = idx & 7;
            cp16(base + swz((uint32_t)(r * 128 + c * 16)),
                 src + (size_t)r * KPAD + c * 8);
        }
    };
    auto loadB = [&](int kt, int slot) {
        const __half* src = g_We + (size_t)n0 * KPAD + (size_t)kt * BK;
        uint32_t base = sb + slot * STAGE + ABYTES;
#pragma unroll
        for (int i = 0; i < 8; i++) {
            int idx = tid + i * 128;
            int r = idx >> 3, c = idx & 7;
            cp16(base + swz((uint32_t)(r * 128 + c * 16)),
                 src + (size_t)r * KPAD + c * 8);
        }
    };

    float acc[4][8][4];
#pragma unroll
    for (int t = 0; t < 4; t++)
#pragma unroll
        for (int n = 0; n < 8; n++)
#pragma unroll
            for (int j = 0; j < 4; j++) acc[t][n][j] = 0.f;

    // Prologue: stages 0,1 committed as separate groups
#pragma unroll
    for (int s = 0; s < S - 1; s++) { loadA(s, s); loadB(s, s); CP_COMMIT(); }

    const uint32_t a_row = (uint32_t)(wm * 64 + (lane & 15));
    const uint32_t a_chk = (uint32_t)(lane >> 4);
    const uint32_t b_row = (uint32_t)(wn * 64 + ((lane >> 4) & 1) * 8 + (lane & 7));
    const uint32_t b_chk = (uint32_t)((lane >> 3) & 1);

    uint32_t af[2][4][4];
    uint32_t bf[2][8][2];

    auto load_frag = [&](int buf, uint32_t abase, int ks) {
        const uint32_t bbase = abase + ABYTES;
#pragma unroll
        for (int t = 0; t < 4; t++) {
            uint32_t off = (a_row + t * 16) * 128 + (a_chk + ks * 2) * 16;
            LDSM4(af[buf][t], abase + swz(off));
        }
#pragma unroll
        for (int g = 0; g < 4; g++) {
            uint32_t off = (b_row + g * 16) * 128 + (b_chk + ks * 2) * 16;
            uint32_t r[4];
            LDSM4(r, bbase + swz(off));
            bf[buf][2 * g][0] = r[0];     bf[buf][2 * g][1] = r[1];
            bf[buf][2 * g + 1][0] = r[2]; bf[buf][2 * g + 1][1] = r[3];
        }
    };
    auto mma_block = [&](int buf) {
#pragma unroll
        for (int t = 0; t < 4; t++)
#pragma unroll
            for (int n = 0; n < 8; n++)
                MMA16816(acc[t][n], af[buf][t], bf[buf][n]);
    };

    // Wait stage 0 (leave stage 1 in flight), prefetch its ks=0 fragments.
    CP_WAIT(1);
    __syncthreads();
    load_frag(0, sb + 0 * STAGE, 0);

    for (int kt = 0; kt < KT; kt++) {
        const uint32_t abase = sb + (kt % S) * STAGE;
        // Barrier: about to overwrite slot (kt+2)%S == (kt-1)%S. All reads of
        // stage kt-1 (and the prefetch read of stage kt) happened before here.
        __syncthreads();

        load_frag(1, abase, 1);          // ks=1 frags first (critical path)
        mma_block(0);                    // ks=0 (prefetched)

        if (kt + 2 < KT) {               // issue next stage UNCOMMITTED
            loadA(kt + 2, (kt + 2) % S);
            loadB(kt + 2, (kt + 2) % S);
        }

        load_frag(0, abase, 2);
        mma_block(1);                    // ks=1

        load_frag(1, abase, 3);
        mma_block(0);                    // ks=2

        if (kt + 1 < KT) {
            CP_WAIT(0);                  // drains stage kt+1 only (kt+2 uncommitted)
            load_frag(0, sb + ((kt + 1) % S) * STAGE, 0);   // prefetch next ks=0
        }
        mma_block(1);                    // ks=3
        CP_COMMIT();                     // name stage kt+2's group
    }

    // Epilogue: direct float2 stores
#pragma unroll
    for (int t = 0; t < 4; t++) {
        const int r0 = m0 + wm * 64 + t * 16 + gid;
        float* y0 = Y + (size_t)r0 * D_OUT + n0 + wn * 64 + tig * 2;
        float* y1 = y0 + (size_t)8 * D_OUT;
#pragma unroll
        for (int n = 0; n < 8; n++) {
            *(float2*)(y0 + n * 8) = make_float2(acc[t][n][0], acc[t][n][1]);
            *(float2*)(y1 + n * 8) = make_float2(acc[t][n][2], acc[t][n][3]);
        }
    }
}

// ------------------------------- launcher ----------------------------------
extern "C" void kernel_launch(void* const* d_in, const int* in_sizes, int n_in,
                              void* d_out, int out_size) {
    const float* X  = (const float*)d_in[0];
    const float* Wq = (const float*)d_in[1];
    const float* c1 = (const float*)d_in[2];
    const float* ck = (const float*)d_in[3];
    const float* L1 = (const float*)d_in[4];
    const float* L2 = (const float*)d_in[5];
    float* Y = (float*)d_out;

    cudaFuncSetAttribute(gemm_kernel, cudaFuncAttributeMaxDynamicSharedMemorySize, SMEM_SZ);

    pack_x_kernel<<<NROWS / 32, 256>>>(X, L1);
    pack_w_kernel<<<dim3(D_OUT / 64, D_IN / 64), 256>>>(Wq, c1, ck);
    pack_tail_kernel<<<(D_OUT * 64) / 256, 256>>>(L2);
    gemm_kernel<<<dim3(D_OUT / BN, NROWS / BM), 128, SMEM_SZ>>>(Y);
}